// round 1
// baseline (speedup 1.0000x reference)
#include <cuda_runtime.h>
#include <cstdint>

// DQ_Add_LayerNorm_Q : fused dequant + residual add + LayerNorm + int8 requant
// rows = 16384, dim = 4096. One block per row, single DRAM pass.

constexpr int TOKENS = 16384;
constexpr int DIM = 4096;
constexpr float EPS = 1e-5f;
constexpr float INPUT_SCALE = 0.01f;

constexpr int THREADS = 256;
constexpr int VEC = 4;                              // float4 / int4
constexpr int ITER = DIM / (THREADS * VEC);         // 4 iterations per thread
constexpr int NWARP = THREADS / 32;

__device__ __forceinline__ float warp_sum(float v) {
#pragma unroll
    for (int off = 16; off > 0; off >>= 1)
        v += __shfl_xor_sync(0xFFFFFFFFu, v, off);
    return v;
}

// Q_AS_FLOAT: harness concatenated outputs as float32 (q cast to float).
// otherwise: byte layout — x fp32 bytes first, then q int8 bytes.
template <bool Q_AS_FLOAT>
__global__ __launch_bounds__(THREADS, 8)
void fused_dq_ln_q_kernel(const float* __restrict__ resid,
                          const int*   __restrict__ qin,
                          const float* __restrict__ weight,
                          const float* __restrict__ bias,
                          float* __restrict__ xout,
                          void*  __restrict__ qout)
{
    const int row = blockIdx.x;
    const int tid = threadIdx.x;
    const size_t base = (size_t)row * DIM;

    const float4* r4 = reinterpret_cast<const float4*>(resid + base);
    const int4*   q4 = reinterpret_cast<const int4*>(qin + base);

    float4 xv[ITER];
    float s = 0.0f, ss = 0.0f;

#pragma unroll
    for (int i = 0; i < ITER; i++) {
        const int idx = tid + i * THREADS;
        float4 r = r4[idx];
        int4   q = q4[idx];
        float4 v;
        v.x = fmaf((float)q.x, INPUT_SCALE, r.x);
        v.y = fmaf((float)q.y, INPUT_SCALE, r.y);
        v.z = fmaf((float)q.z, INPUT_SCALE, r.z);
        v.w = fmaf((float)q.w, INPUT_SCALE, r.w);
        xv[i] = v;
        s  += (v.x + v.y) + (v.z + v.w);
        ss += fmaf(v.x, v.x, v.y * v.y) + fmaf(v.z, v.z, v.w * v.w);
    }

    // block reduction of s, ss
    __shared__ float sh_s[NWARP], sh_ss[NWARP];
    float ws  = warp_sum(s);
    float wss = warp_sum(ss);
    const int lane = tid & 31, wid = tid >> 5;
    if (lane == 0) { sh_s[wid] = ws; sh_ss[wid] = wss; }
    __syncthreads();
    float ts = 0.0f, tss = 0.0f;
    if (wid == 0) {
        float a = (lane < NWARP) ? sh_s[lane]  : 0.0f;
        float b = (lane < NWARP) ? sh_ss[lane] : 0.0f;
#pragma unroll
        for (int off = NWARP / 2; off > 0; off >>= 1) {
            a += __shfl_xor_sync(0xFFFFFFFFu, a, off);
            b += __shfl_xor_sync(0xFFFFFFFFu, b, off);
        }
        if (lane == 0) { sh_s[0] = a; sh_ss[0] = b; }
    }
    __syncthreads();
    ts = sh_s[0]; tss = sh_ss[0];

    const float mean = ts * (1.0f / DIM);
    const float var  = fmaf(-mean, mean, tss * (1.0f / DIM));
    const float inv  = rsqrtf(var + EPS);

    // write updated residual x
    float4* xo4 = reinterpret_cast<float4*>(xout + base);
#pragma unroll
    for (int i = 0; i < ITER; i++)
        xo4[tid + i * THREADS] = xv[i];

    // affine + quantize
    const float4* w4 = reinterpret_cast<const float4*>(weight);
    const float4* b4 = reinterpret_cast<const float4*>(bias);
#pragma unroll
    for (int i = 0; i < ITER; i++) {
        const int idx = tid + i * THREADS;
        float4 w = __ldg(&w4[idx]);
        float4 b = __ldg(&b4[idx]);
        float4 v = xv[i];
        float lx = fmaf((v.x - mean) * inv, w.x, b.x);
        float ly = fmaf((v.y - mean) * inv, w.y, b.y);
        float lz = fmaf((v.z - mean) * inv, w.z, b.z);
        float lw = fmaf((v.w - mean) * inv, w.w, b.w);
        // jnp.round = round-half-to-even -> rintf, then clip
        float qx = fminf(fmaxf(rintf(lx), -128.0f), 127.0f);
        float qy = fminf(fmaxf(rintf(ly), -128.0f), 127.0f);
        float qz = fminf(fmaxf(rintf(lz), -128.0f), 127.0f);
        float qw = fminf(fmaxf(rintf(lw), -128.0f), 127.0f);
        if (Q_AS_FLOAT) {
            float4* qo = reinterpret_cast<float4*>((float*)qout + base);
            qo[idx] = make_float4(qx, qy, qz, qw);
        } else {
            char4* qo = reinterpret_cast<char4*>((int8_t*)qout + base);
            char4 c;
            c.x = (signed char)(int)qx;
            c.y = (signed char)(int)qy;
            c.z = (signed char)(int)qz;
            c.w = (signed char)(int)qw;
            qo[idx] = c;
        }
    }
}

extern "C" void kernel_launch(void* const* d_in, const int* in_sizes, int n_in,
                              void* d_out, int out_size) {
    const float* resid  = (const float*)d_in[0];
    const int*   qin    = (const int*)d_in[1];
    const float* weight = (const float*)d_in[2];
    const float* bias   = (const float*)d_in[3];

    const size_t N = (size_t)TOKENS * DIM;
    float* xout = (float*)d_out;

    if ((size_t)out_size == 2 * N) {
        // outputs concatenated as float32: [x fp32 | q cast to fp32]
        void* qout = (void*)(xout + N);
        fused_dq_ln_q_kernel<true><<<TOKENS, THREADS>>>(resid, qin, weight, bias, xout, qout);
    } else {
        // byte layout: [x fp32 bytes | q int8 bytes]
        void* qout = (void*)((int8_t*)d_out + N * sizeof(float));
        fused_dq_ln_q_kernel<false><<<TOKENS, THREADS>>>(resid, qin, weight, bias, xout, qout);
    }
}

// round 2
// speedup vs baseline: 1.0445x; 1.0445x over previous
#include <cuda_runtime.h>
#include <cstdint>

// DQ_Add_LayerNorm_Q : fused dequant + residual add + LayerNorm + int8 requant
// rows = 16384, dim = 4096. One block per row, single DRAM pass.
// R2: relax reg cap (occ 8 -> 4) for front-batched load MLP; streaming cache hints.

constexpr int TOKENS = 16384;
constexpr int DIM = 4096;
constexpr float EPS = 1e-5f;
constexpr float INPUT_SCALE = 0.01f;

constexpr int THREADS = 256;
constexpr int VEC = 4;                              // float4 / int4
constexpr int ITER = DIM / (THREADS * VEC);         // 4 iterations per thread
constexpr int NWARP = THREADS / 32;

__device__ __forceinline__ float warp_sum(float v) {
#pragma unroll
    for (int off = 16; off > 0; off >>= 1)
        v += __shfl_xor_sync(0xFFFFFFFFu, v, off);
    return v;
}

// Q_AS_FLOAT: harness concatenated outputs as float32 (q cast to float).
// otherwise: byte layout — x fp32 bytes first, then q int8 bytes.
template <bool Q_AS_FLOAT>
__global__ __launch_bounds__(THREADS, 4)
void fused_dq_ln_q_kernel(const float* __restrict__ resid,
                          const int*   __restrict__ qin,
                          const float* __restrict__ weight,
                          const float* __restrict__ bias,
                          float* __restrict__ xout,
                          void*  __restrict__ qout)
{
    const int row = blockIdx.x;
    const int tid = threadIdx.x;
    const size_t base = (size_t)row * DIM;

    const float4* r4 = reinterpret_cast<const float4*>(resid + base);
    const int4*   q4 = reinterpret_cast<const int4*>(qin + base);

    // Front-batch ALL loads: 8 independent 128-bit LDGs in flight per thread.
    float4 rv[ITER];
    int4   qv[ITER];
#pragma unroll
    for (int i = 0; i < ITER; i++) {
        const int idx = tid + i * THREADS;
        rv[i] = __ldcs(&r4[idx]);   // streaming: no reuse
        qv[i] = __ldcs(&q4[idx]);
    }

    float4 xv[ITER];
    float s = 0.0f, ss = 0.0f;
#pragma unroll
    for (int i = 0; i < ITER; i++) {
        float4 v;
        v.x = fmaf((float)qv[i].x, INPUT_SCALE, rv[i].x);
        v.y = fmaf((float)qv[i].y, INPUT_SCALE, rv[i].y);
        v.z = fmaf((float)qv[i].z, INPUT_SCALE, rv[i].z);
        v.w = fmaf((float)qv[i].w, INPUT_SCALE, rv[i].w);
        xv[i] = v;
        s  += (v.x + v.y) + (v.z + v.w);
        ss += fmaf(v.x, v.x, v.y * v.y) + fmaf(v.z, v.z, v.w * v.w);
    }

    // Write updated residual x immediately (fire-and-forget, overlaps reduction).
    float4* xo4 = reinterpret_cast<float4*>(xout + base);
#pragma unroll
    for (int i = 0; i < ITER; i++)
        __stcs(&xo4[tid + i * THREADS], xv[i]);

    // block reduction of s, ss
    __shared__ float sh_s[NWARP], sh_ss[NWARP];
    float ws  = warp_sum(s);
    float wss = warp_sum(ss);
    const int lane = tid & 31, wid = tid >> 5;
    if (lane == 0) { sh_s[wid] = ws; sh_ss[wid] = wss; }
    __syncthreads();
    if (wid == 0) {
        float a = (lane < NWARP) ? sh_s[lane]  : 0.0f;
        float b = (lane < NWARP) ? sh_ss[lane] : 0.0f;
#pragma unroll
        for (int off = NWARP / 2; off > 0; off >>= 1) {
            a += __shfl_xor_sync(0xFFFFFFFFu, a, off);
            b += __shfl_xor_sync(0xFFFFFFFFu, b, off);
        }
        if (lane == 0) { sh_s[0] = a; sh_ss[0] = b; }
    }
    __syncthreads();
    const float ts = sh_s[0], tss = sh_ss[0];

    const float mean = ts * (1.0f / DIM);
    const float var  = fmaf(-mean, mean, tss * (1.0f / DIM));
    const float inv  = rsqrtf(var + EPS);

    // affine + quantize
    const float4* w4 = reinterpret_cast<const float4*>(weight);
    const float4* b4 = reinterpret_cast<const float4*>(bias);
#pragma unroll
    for (int i = 0; i < ITER; i++) {
        const int idx = tid + i * THREADS;
        float4 w = __ldg(&w4[idx]);   // reused across all rows: keep cached
        float4 b = __ldg(&b4[idx]);
        float4 v = xv[i];
        float lx = fmaf((v.x - mean) * inv, w.x, b.x);
        float ly = fmaf((v.y - mean) * inv, w.y, b.y);
        float lz = fmaf((v.z - mean) * inv, w.z, b.z);
        float lw = fmaf((v.w - mean) * inv, w.w, b.w);
        // jnp.round = round-half-to-even -> rintf, then clip
        float qx = fminf(fmaxf(rintf(lx), -128.0f), 127.0f);
        float qy = fminf(fmaxf(rintf(ly), -128.0f), 127.0f);
        float qz = fminf(fmaxf(rintf(lz), -128.0f), 127.0f);
        float qw = fminf(fmaxf(rintf(lw), -128.0f), 127.0f);
        if (Q_AS_FLOAT) {
            float4* qo = reinterpret_cast<float4*>((float*)qout + base);
            __stcs(&qo[idx], make_float4(qx, qy, qz, qw));
        } else {
            char4* qo = reinterpret_cast<char4*>((int8_t*)qout + base);
            char4 c;
            c.x = (signed char)(int)qx;
            c.y = (signed char)(int)qy;
            c.z = (signed char)(int)qz;
            c.w = (signed char)(int)qw;
            qo[idx] = c;
        }
    }
}

extern "C" void kernel_launch(void* const* d_in, const int* in_sizes, int n_in,
                              void* d_out, int out_size) {
    const float* resid  = (const float*)d_in[0];
    const int*   qin    = (const int*)d_in[1];
    const float* weight = (const float*)d_in[2];
    const float* bias   = (const float*)d_in[3];

    const size_t N = (size_t)TOKENS * DIM;
    float* xout = (float*)d_out;

    if ((size_t)out_size == 2 * N) {
        // outputs concatenated as float32: [x fp32 | q cast to fp32]
        void* qout = (void*)(xout + N);
        fused_dq_ln_q_kernel<true><<<TOKENS, THREADS>>>(resid, qin, weight, bias, xout, qout);
    } else {
        // byte layout: [x fp32 bytes | q int8 bytes]
        void* qout = (void*)((int8_t*)d_out + N * sizeof(float));
        fused_dq_ln_q_kernel<false><<<TOKENS, THREADS>>>(resid, qin, weight, bias, xout, qout);
    }
}